// round 5
// baseline (speedup 1.0000x reference)
#include <cuda_runtime.h>
#include <math_constants.h>

// LSS view transformer, GB300 sm_103a — atomic-free gather formulation v2.
//
// Empirics so far: L2 atomic path costs ~13x more per byte than plain ld/st
// (R2 scalar reds == R4 v4 reds == ~90us for 43MB). So: no atomics.
//
// k0 tables: per-d inversion of the static monotone maps ix(w,d), iy(h,d):
//            pixels feeding voxel (iy,ix) at depth d form a rectangle.
// k1 lift:   per-pixel softmax over depth (6 cams) + combined value
//            T[d][p][c] = sum_cam prob*feat, plain coalesced stores (~57MB).
// k2 splat:  block = (32 ix, 1 iy, channel-half). Sum T over (d, rect) with
//            coalesced 256B reads (T is L2-resident), smem transpose,
//            coalesced channel-major output writes. Covers every output
//            element -> no output memset needed.

#define D_N   40
#define H_N   32
#define W_N   88
#define CAM_N 6
#define C_N   128
#define BEV   125
#define NPIX  (H_N * W_N)
#define NVOX  (BEV * BEV)

__device__ float g_T[(size_t)D_N * NPIX * C_N];   // (d, pixel, c) ~57.7MB
__device__ int g_wlo[D_N * BEV];
__device__ int g_whi[D_N * BEV];
__device__ int g_hlo[D_N * BEV];
__device__ int g_hhi[D_N * BEV];

// Exact fp32 op sequence of the reference (unfused; no FMA contraction).
__device__ __forceinline__ int ix_of(int w, float dv) {
    float xd = __fmul_rn((float)w, dv);
    float gx = __fadd_rn(__fmul_rn(__fdiv_rn(xd, 3567.0f), 100.0f), -50.0f);
    return (int)__fdiv_rn(__fadd_rn(gx, 50.0f), 0.8f);
}
__device__ __forceinline__ int iy_of(int h, float dv) {
    float yd = __fmul_rn((float)h, dv);
    float gy = __fadd_rn(__fmul_rn(__fdiv_rn(yd, 1271.0f), 100.0f), -50.0f);
    return (int)__fdiv_rn(__fadd_rn(gy, 50.0f), 0.8f);
}

// ---- k0: per-d inversion tables (fully parallel) ---------------------------
__global__ void build_tables_kernel() {
    const int d = blockIdx.x;
    const int t = threadIdx.x;
    const float dv = (float)(d + 2);
    __shared__ int s_ix[W_N];
    __shared__ int s_iy[H_N];

    for (int i = t; i < BEV; i += 128) {
        g_wlo[d * BEV + i] = 0; g_whi[d * BEV + i] = 0;
        g_hlo[d * BEV + i] = 0; g_hhi[d * BEV + i] = 0;
    }
    if (t < W_N) s_ix[t] = ix_of(t, dv);
    if (t >= 96 && t < 96 + H_N) s_iy[t - 96] = iy_of(t - 96, dv);
    __syncthreads();

    if (t < W_N) {                              // boundaries of equal-ix runs
        int ix = s_ix[t];
        if (ix < BEV) {
            if (t == 0       || s_ix[t - 1] != ix) g_wlo[d * BEV + ix] = t;
            if (t == W_N - 1 || s_ix[t + 1] != ix) g_whi[d * BEV + ix] = t + 1;
        }
    } else if (t >= 96 && t < 96 + H_N) {
        int h = t - 96;
        int iy = s_iy[h];
        if (iy < BEV) {
            if (h == 0       || s_iy[h - 1] != iy) g_hlo[d * BEV + iy] = h;
            if (h == H_N - 1 || s_iy[h + 1] != iy) g_hhi[d * BEV + iy] = h + 1;
        }
    }
}

// ---- k1: softmax + lift (plain coalesced stores) ----------------------------
__global__ __launch_bounds__(256, 8) void lift_kernel(
    const float* __restrict__ img_feat,
    const float* __restrict__ depth_logits)
{
    __shared__ float s_p[CAM_N][D_N];
    __shared__ float s_mx[CAM_N], s_inv[CAM_N];
    __shared__ int   s_dmax;

    const int p   = blockIdx.x;
    const int h   = p / W_N;
    const int w   = p - h * W_N;
    const int tid = threadIdx.x;
    const int cam = tid / D_N;
    const int d   = tid - cam * D_N;

    if (tid < CAM_N * D_N)
        s_p[cam][d] = depth_logits[((cam * D_N + d) * H_N + h) * W_N + w];
    __syncthreads();

    if (tid < CAM_N) {
        float m = -CUDART_INF_F;
        #pragma unroll
        for (int i = 0; i < D_N; ++i) m = fmaxf(m, s_p[tid][i]);
        s_mx[tid] = m;
    }
    __syncthreads();
    if (tid < CAM_N * D_N)
        s_p[cam][d] = __expf(s_p[cam][d] - s_mx[cam]);
    __syncthreads();
    if (tid < CAM_N) {
        float s = 0.0f;
        #pragma unroll
        for (int i = 0; i < D_N; ++i) s += s_p[tid][i];
        s_inv[tid] = 1.0f / s;
    }
    if (tid == CAM_N) {                  // validity is a prefix in d
        int dm = D_N;
        for (int i = 0; i < D_N; ++i) {
            float dv = (float)(i + 2);
            if (ix_of(w, dv) >= BEV || iy_of(h, dv) >= BEV) { dm = i; break; }
        }
        s_dmax = dm;
    }
    __syncthreads();
    if (tid < CAM_N * D_N)
        s_p[cam][d] *= s_inv[cam];
    __syncthreads();

    const int c    = tid & (C_N - 1);
    const int half = tid >> 7;
    const int fb   = (c * H_N + h) * W_N + w;
    const int FS   = C_N * H_N * W_N;
    const float f0 = img_feat[fb + 0 * FS];
    const float f1 = img_feat[fb + 1 * FS];
    const float f2 = img_feat[fb + 2 * FS];
    const float f3 = img_feat[fb + 3 * FS];
    const float f4 = img_feat[fb + 4 * FS];
    const float f5 = img_feat[fb + 5 * FS];

    const int dmax = s_dmax;
    for (int dd = half; dd < dmax; dd += 2) {
        float val = s_p[0][dd] * f0 + s_p[1][dd] * f1 + s_p[2][dd] * f2
                  + s_p[3][dd] * f3 + s_p[4][dd] * f4 + s_p[5][dd] * f5;
        g_T[((size_t)dd * NPIX + p) * C_N + c] = val;
    }
}

// ---- k2: gather/splat, balanced ---------------------------------------------
// grid = (4 ix-groups, 125 iy, 2 channel-halves), block = 256.
// Warp `wid` handles voxels ix0 + wid + 8k (interleaved for balance), lanes
// cover 64 channels via float2 (coalesced 256B per entry per warp).
__global__ __launch_bounds__(256) void splat_kernel(float* __restrict__ out)
{
    const int iy   = blockIdx.y;
    const int ix0  = blockIdx.x * 32;
    const int z    = blockIdx.z;          // channel half
    const int tid  = threadIdx.x;
    const int lane = tid & 31;
    const int wid  = tid >> 5;

    __shared__ int   s_hlo[D_N], s_hhi[D_N];
    __shared__ int   s_wlo[D_N][32], s_whi[D_N][32];
    __shared__ float s_acc[32][65];       // [voxel][channel-in-half], pad 1

    for (int i = tid; i < D_N; i += 256) {
        s_hlo[i] = g_hlo[i * BEV + iy];
        s_hhi[i] = g_hhi[i * BEV + iy];
    }
    for (int i = tid; i < D_N * 32; i += 256) {
        int d = i >> 5, j = i & 31;
        int ixx = ix0 + j;
        s_wlo[d][j] = (ixx < BEV) ? g_wlo[d * BEV + ixx] : 0;
        s_whi[d][j] = (ixx < BEV) ? g_whi[d * BEV + ixx] : 0;
    }
    __syncthreads();

    const float2* Tb = reinterpret_cast<const float2*>(g_T)
                     + (size_t)z * 32 + lane;     // + (d*NPIX+p)*64

    #pragma unroll
    for (int k = 0; k < 4; ++k) {
        const int v = wid + 8 * k;                // voxel slot 0..31
        float ax = 0.0f, ay = 0.0f;
        #pragma unroll 1
        for (int d = 0; d < D_N; ++d) {
            const int hl = s_hlo[d], hh = s_hhi[d];
            if (hl >= hh) continue;
            const int wl = s_wlo[d][v], wh = s_whi[d][v];
            const float2* base = Tb + (size_t)d * NPIX * 64;
            for (int h = hl; h < hh; ++h) {
                const float2* row = base + (size_t)(h * W_N) * 64;
                for (int w = wl; w < wh; ++w) {
                    float2 t = row[(size_t)w * 64];
                    ax += t.x; ay += t.y;
                }
            }
        }
        s_acc[v][2 * lane + 0] = ax;
        s_acc[v][2 * lane + 1] = ay;
    }
    __syncthreads();

    // transposed write: consecutive lanes -> consecutive ix (coalesced)
    const int vl  = tid & 31;
    const int ixx = ix0 + vl;
    if (ixx < BEV) {
        for (int cl = wid; cl < 64; cl += 8)
            out[(size_t)(z * 64 + cl) * NVOX + iy * BEV + ixx] = s_acc[vl][cl];
    }
}

extern "C" void kernel_launch(void* const* d_in, const int* in_sizes, int n_in,
                              void* d_out, int out_size)
{
    const float* img_feat     = (const float*)d_in[0];
    const float* depth_logits = (const float*)d_in[1];
    float* out = (float*)d_out;

    build_tables_kernel<<<D_N, 128>>>();
    lift_kernel<<<NPIX, 256>>>(img_feat, depth_logits);
    splat_kernel<<<dim3(4, BEV, 2), 256>>>(out);
}

// round 6
// speedup vs baseline: 1.1722x; 1.1722x over previous
#include <cuda_runtime.h>
#include <math_constants.h>

// LSS view transformer, GB300 sm_103a — balanced CSR gather.
//
// Model so far: L2 atomics ~0.5 B/cyc (13x worse than plain ld/st) -> R2/R4
// scatter stuck ~100us. Naive per-voxel gather (R3/R5) dies on hot-corner
// load imbalance + MLP=1. Fix: static CSR over voxels, splat warps own
// FIXED-SIZE entry chunks (perfect balance), segmented reduction with plain
// stores for interior voxels and v2 REDs only at chunk boundaries.
//
// k0 tables   : per-d inversion of monotone ix(w,d), iy(h,d) (rectangles)
// k1 counts   : per-voxel entry count from tables
// k2 scan     : exclusive prefix sum -> g_vstart (single block)
// k3 fill     : CSR entry list (pixOff, voxel)
// k4 lift     : softmax + T[d][p][c] = sum_cam prob*feat (coalesced stores)
// k5 splat    : chunked segmented reduction into g_acc (voxel-major)
// k6 transpose: g_acc -> out (channel-major), covers all elements

#define D_N   40
#define H_N   32
#define W_N   88
#define CAM_N 6
#define C_N   128
#define BEV   125
#define NPIX  (H_N * W_N)          // 2816
#define NVOX  (BEV * BEV)          // 15625
#define NENT  (D_N * NPIX)         // 112640 (upper bound == exact-ish)
#define CHUNK 64
#define NCHUNK ((NENT + CHUNK - 1) / CHUNK)   // 1760

__device__ float g_T[(size_t)D_N * NPIX * C_N];   // ~57.7MB
__device__ float g_acc[(size_t)NVOX * C_N];       // ~8MB (voxel, channel)
__device__ int   g_wlo[D_N * BEV], g_whi[D_N * BEV];
__device__ int   g_hlo[D_N * BEV], g_hhi[D_N * BEV];
__device__ int   g_cnt[NVOX];
__device__ int   g_vstart[NVOX + 1];
__device__ int2  g_entries[NENT];

// Exact fp32 op sequence of the reference (unfused; no FMA contraction).
__device__ __forceinline__ int ix_of(int w, float dv) {
    float xd = __fmul_rn((float)w, dv);
    float gx = __fadd_rn(__fmul_rn(__fdiv_rn(xd, 3567.0f), 100.0f), -50.0f);
    return (int)__fdiv_rn(__fadd_rn(gx, 50.0f), 0.8f);
}
__device__ __forceinline__ int iy_of(int h, float dv) {
    float yd = __fmul_rn((float)h, dv);
    float gy = __fadd_rn(__fmul_rn(__fdiv_rn(yd, 1271.0f), 100.0f), -50.0f);
    return (int)__fdiv_rn(__fadd_rn(gy, 50.0f), 0.8f);
}

// ---- k0: per-d inversion tables ---------------------------------------------
__global__ void build_tables_kernel() {
    const int d = blockIdx.x;
    const int t = threadIdx.x;
    const float dv = (float)(d + 2);
    __shared__ int s_ix[W_N];
    __shared__ int s_iy[H_N];

    if (t < BEV) {
        g_wlo[d * BEV + t] = 0; g_whi[d * BEV + t] = 0;
        g_hlo[d * BEV + t] = 0; g_hhi[d * BEV + t] = 0;
    }
    if (t < W_N) s_ix[t] = ix_of(t, dv);
    if (t >= 96 && t < 96 + H_N) s_iy[t - 96] = iy_of(t - 96, dv);
    __syncthreads();

    if (t < W_N) {
        int ix = s_ix[t];
        if (ix < BEV) {
            if (t == 0       || s_ix[t - 1] != ix) g_wlo[d * BEV + ix] = t;
            if (t == W_N - 1 || s_ix[t + 1] != ix) g_whi[d * BEV + ix] = t + 1;
        }
    } else if (t >= 96 && t < 96 + H_N) {
        int h = t - 96;
        int iy = s_iy[h];
        if (iy < BEV) {
            if (h == 0       || s_iy[h - 1] != iy) g_hlo[d * BEV + iy] = h;
            if (h == H_N - 1 || s_iy[h + 1] != iy) g_hhi[d * BEV + iy] = h + 1;
        }
    }
}

// ---- k1: per-voxel counts ---------------------------------------------------
__global__ void count_kernel() {
    const int v = blockIdx.x * blockDim.x + threadIdx.x;
    if (v >= NVOX) return;
    const int iy = v / BEV, ix = v - iy * BEV;
    int cnt = 0;
    #pragma unroll
    for (int d = 0; d < D_N; ++d)
        cnt += (g_hhi[d * BEV + iy] - g_hlo[d * BEV + iy]) *
               (g_whi[d * BEV + ix] - g_wlo[d * BEV + ix]);
    g_cnt[v] = cnt;
}

// ---- k2: exclusive scan (single block, 1024 threads x 16 voxels) -------------
__global__ __launch_bounds__(1024) void scan_kernel() {
    __shared__ int sh[1024];
    const int t = threadIdx.x;
    int local[16], lsum = 0;
    #pragma unroll
    for (int j = 0; j < 16; ++j) {
        int v = t * 16 + j;
        int c = (v < NVOX) ? g_cnt[v] : 0;
        local[j] = lsum; lsum += c;
    }
    sh[t] = lsum;
    __syncthreads();
    for (int off = 1; off < 1024; off <<= 1) {
        int x = (t >= off) ? sh[t - off] : 0;
        __syncthreads();
        sh[t] += x;
        __syncthreads();
    }
    int base = sh[t] - lsum;     // exclusive
    #pragma unroll
    for (int j = 0; j < 16; ++j) {
        int v = t * 16 + j;
        if (v < NVOX) g_vstart[v] = base + local[j];
    }
    if (t == 1023) g_vstart[NVOX] = sh[1023];
}

// ---- k3: fill CSR entry list --------------------------------------------------
__global__ void fill_kernel() {
    const int v = blockIdx.x * blockDim.x + threadIdx.x;
    if (v >= NVOX) return;
    const int iy = v / BEV, ix = v - iy * BEV;
    int pos = g_vstart[v];
    for (int d = 0; d < D_N; ++d) {
        const int hl = g_hlo[d * BEV + iy], hh = g_hhi[d * BEV + iy];
        const int wl = g_wlo[d * BEV + ix], wh = g_whi[d * BEV + ix];
        for (int h = hl; h < hh; ++h)
            for (int w = wl; w < wh; ++w)
                g_entries[pos++] = make_int2(d * NPIX + h * W_N + w, v);
    }
}

// ---- k4: softmax + lift -------------------------------------------------------
__global__ __launch_bounds__(256, 8) void lift_kernel(
    const float* __restrict__ img_feat,
    const float* __restrict__ depth_logits)
{
    __shared__ float s_p[CAM_N][D_N];
    __shared__ float s_mx[CAM_N], s_inv[CAM_N];
    __shared__ int   s_dmax;

    const int p   = blockIdx.x;
    const int h   = p / W_N;
    const int w   = p - h * W_N;
    const int tid = threadIdx.x;
    const int cam = tid / D_N;
    const int d   = tid - cam * D_N;

    if (tid < CAM_N * D_N)
        s_p[cam][d] = depth_logits[((cam * D_N + d) * H_N + h) * W_N + w];
    __syncthreads();

    if (tid < CAM_N) {
        float m = -CUDART_INF_F;
        #pragma unroll
        for (int i = 0; i < D_N; ++i) m = fmaxf(m, s_p[tid][i]);
        s_mx[tid] = m;
    }
    __syncthreads();
    if (tid < CAM_N * D_N)
        s_p[cam][d] = __expf(s_p[cam][d] - s_mx[cam]);
    __syncthreads();
    if (tid < CAM_N) {
        float s = 0.0f;
        #pragma unroll
        for (int i = 0; i < D_N; ++i) s += s_p[tid][i];
        s_inv[tid] = 1.0f / s;
    }
    if (tid == CAM_N) {                  // validity is a prefix in d
        int dm = D_N;
        for (int i = 0; i < D_N; ++i) {
            float dv = (float)(i + 2);
            if (ix_of(w, dv) >= BEV || iy_of(h, dv) >= BEV) { dm = i; break; }
        }
        s_dmax = dm;
    }
    __syncthreads();
    if (tid < CAM_N * D_N)
        s_p[cam][d] *= s_inv[cam];
    __syncthreads();

    const int c    = tid & (C_N - 1);
    const int half = tid >> 7;
    const int fb   = (c * H_N + h) * W_N + w;
    const int FS   = C_N * H_N * W_N;
    const float f0 = img_feat[fb + 0 * FS];
    const float f1 = img_feat[fb + 1 * FS];
    const float f2 = img_feat[fb + 2 * FS];
    const float f3 = img_feat[fb + 3 * FS];
    const float f4 = img_feat[fb + 4 * FS];
    const float f5 = img_feat[fb + 5 * FS];

    const int dmax = s_dmax;
    for (int dd = half; dd < dmax; dd += 2) {
        float val = s_p[0][dd] * f0 + s_p[1][dd] * f1 + s_p[2][dd] * f2
                  + s_p[3][dd] * f3 + s_p[4][dd] * f4 + s_p[5][dd] * f5;
        g_T[((size_t)dd * NPIX + p) * C_N + c] = val;
    }
}

// ---- k5: chunked segmented splat ---------------------------------------------
// warp gw: z = gw&1 (channel half), chunk = gw>>1. lanes = 64 channels (float2).
__global__ __launch_bounds__(256) void splat_kernel()
{
    const int gw   = (blockIdx.x * blockDim.x + threadIdx.x) >> 5;
    const int lane = threadIdx.x & 31;
    const int z    = gw & 1;
    const int chunk = gw >> 1;

    const int total = g_vstart[NVOX];
    const int s0 = chunk * CHUNK;
    if (s0 >= total) return;
    const int s1 = min(s0 + CHUNK, total);

    const int prev_vox = (s0 > 0)     ? __ldg(&g_entries[s0 - 1]).y : -1;
    const int next_vox = (s1 < total) ? __ldg(&g_entries[s1]).y     : -1;

    const float2* __restrict__ T2 = reinterpret_cast<const float2*>(g_T);
    const int coff = z * 32 + lane;

    int2 e = __ldg(&g_entries[s0]);
    int  cur = e.y;
    bool first_seg = true;
    float ax = 0.0f, ay = 0.0f;

    for (int i = s0; i < s1; ++i) {
        float2 t = T2[(size_t)e.x * 64 + coff];
        int2 en = (i + 1 < s1) ? __ldg(&g_entries[i + 1]) : make_int2(0, -1);
        ax += t.x; ay += t.y;
        if (en.y != cur) {
            const bool partial = (first_seg && cur == prev_vox) ||
                                 (i + 1 == s1 && cur == next_vox);
            float* dst = g_acc + (size_t)cur * C_N + 2 * coff;
            if (partial) {
                asm volatile("red.global.add.v2.f32 [%0], {%1,%2};"
                             :: "l"(dst), "f"(ax), "f"(ay) : "memory");
            } else {
                *reinterpret_cast<float2*>(dst) = make_float2(ax, ay);
            }
            ax = 0.0f; ay = 0.0f;
            first_seg = false;
            cur = en.y;
        }
        e = en;
    }
}

// ---- k6: transpose g_acc (voxel-major) -> out (channel-major) -----------------
__global__ __launch_bounds__(256) void transpose_kernel(float* __restrict__ out)
{
    __shared__ float s[32][65];
    const int v0  = blockIdx.x * 32;
    const int z   = blockIdx.y;          // channel half
    const int tid = threadIdx.x;

    // read: consecutive threads -> consecutive channels (coalesced 256B)
    const int rc = tid & 63;             // channel-in-half
    const int rv = tid >> 6;             // 0..3
    #pragma unroll
    for (int j = 0; j < 8; ++j) {
        int vl = rv + 4 * j;
        int v  = v0 + vl;
        s[vl][rc] = (v < NVOX) ? g_acc[(size_t)v * C_N + z * 64 + rc] : 0.0f;
    }
    __syncthreads();

    // write: consecutive lanes -> consecutive voxels (coalesced 128B)
    const int vl = tid & 31;
    const int cb = tid >> 5;
    const int v  = v0 + vl;
    if (v < NVOX) {
        #pragma unroll
        for (int c = 0; c < 8; ++c)
            out[(size_t)(z * 64 + cb + 8 * c) * NVOX + v] = s[vl][cb + 8 * c];
    }
}

extern "C" void kernel_launch(void* const* d_in, const int* in_sizes, int n_in,
                              void* d_out, int out_size)
{
    const float* img_feat     = (const float*)d_in[0];
    const float* depth_logits = (const float*)d_in[1];
    float* out = (float*)d_out;

    void* acc_ptr = nullptr;
    cudaGetSymbolAddress(&acc_ptr, g_acc);
    cudaMemsetAsync(acc_ptr, 0, (size_t)NVOX * C_N * sizeof(float), 0);

    build_tables_kernel<<<D_N, 128>>>();
    count_kernel<<<(NVOX + 255) / 256, 256>>>();
    scan_kernel<<<1, 1024>>>();
    fill_kernel<<<(NVOX + 255) / 256, 256>>>();
    lift_kernel<<<NPIX, 256>>>(img_feat, depth_logits);
    splat_kernel<<<(2 * NCHUNK * 32 + 255) / 256, 256>>>();   // 440 blocks
    transpose_kernel<<<dim3((NVOX + 31) / 32, 2), 256>>>(out);
}

// round 7
// speedup vs baseline: 1.2678x; 1.0816x over previous
#include <cuda_runtime.h>
#include <math_constants.h>

// LSS view transformer, GB300 sm_103a — balanced CSR gather.
//
// Model so far: L2 atomics ~0.5 B/cyc (13x worse than plain ld/st) -> R2/R4
// scatter stuck ~100us. Naive per-voxel gather (R3/R5) dies on hot-corner
// load imbalance + MLP=1. Fix: static CSR over voxels, splat warps own
// FIXED-SIZE entry chunks (perfect balance), segmented reduction with plain
// stores for interior voxels and v2 REDs only at chunk boundaries.
//
// k0 tables   : per-d inversion of monotone ix(w,d), iy(h,d) (rectangles)
// k1 counts   : per-voxel entry count from tables
// k2 scan     : exclusive prefix sum -> g_vstart (single block)
// k3 fill     : CSR entry list (pixOff, voxel)
// k4 lift     : softmax + T[d][p][c] = sum_cam prob*feat (coalesced stores)
// k5 splat    : chunked segmented reduction into g_acc (voxel-major)
// k6 transpose: g_acc -> out (channel-major), covers all elements

#define D_N   40
#define H_N   32
#define W_N   88
#define CAM_N 6
#define C_N   128
#define BEV   125
#define NPIX  (H_N * W_N)          // 2816
#define NVOX  (BEV * BEV)          // 15625
#define NENT  (D_N * NPIX)         // 112640 (upper bound == exact-ish)
#define CHUNK 64
#define NCHUNK ((NENT + CHUNK - 1) / CHUNK)   // 1760

__device__ float g_T[(size_t)D_N * NPIX * C_N];   // ~57.7MB
__device__ float g_acc[(size_t)NVOX * C_N];       // ~8MB (voxel, channel)
__device__ int   g_wlo[D_N * BEV], g_whi[D_N * BEV];
__device__ int   g_hlo[D_N * BEV], g_hhi[D_N * BEV];
__device__ int   g_cnt[NVOX];
__device__ int   g_vstart[NVOX + 1];
__device__ int2  g_entries[NENT];

// Exact fp32 op sequence of the reference (unfused; no FMA contraction).
__device__ __forceinline__ int ix_of(int w, float dv) {
    float xd = __fmul_rn((float)w, dv);
    float gx = __fadd_rn(__fmul_rn(__fdiv_rn(xd, 3567.0f), 100.0f), -50.0f);
    return (int)__fdiv_rn(__fadd_rn(gx, 50.0f), 0.8f);
}
__device__ __forceinline__ int iy_of(int h, float dv) {
    float yd = __fmul_rn((float)h, dv);
    float gy = __fadd_rn(__fmul_rn(__fdiv_rn(yd, 1271.0f), 100.0f), -50.0f);
    return (int)__fdiv_rn(__fadd_rn(gy, 50.0f), 0.8f);
}

// ---- k0: per-d inversion tables ---------------------------------------------
__global__ void build_tables_kernel() {
    const int d = blockIdx.x;
    const int t = threadIdx.x;
    const float dv = (float)(d + 2);
    __shared__ int s_ix[W_N];
    __shared__ int s_iy[H_N];

    if (t < BEV) {
        g_wlo[d * BEV + t] = 0; g_whi[d * BEV + t] = 0;
        g_hlo[d * BEV + t] = 0; g_hhi[d * BEV + t] = 0;
    }
    if (t < W_N) s_ix[t] = ix_of(t, dv);
    if (t >= 96 && t < 96 + H_N) s_iy[t - 96] = iy_of(t - 96, dv);
    __syncthreads();

    if (t < W_N) {
        int ix = s_ix[t];
        if (ix < BEV) {
            if (t == 0       || s_ix[t - 1] != ix) g_wlo[d * BEV + ix] = t;
            if (t == W_N - 1 || s_ix[t + 1] != ix) g_whi[d * BEV + ix] = t + 1;
        }
    } else if (t >= 96 && t < 96 + H_N) {
        int h = t - 96;
        int iy = s_iy[h];
        if (iy < BEV) {
            if (h == 0       || s_iy[h - 1] != iy) g_hlo[d * BEV + iy] = h;
            if (h == H_N - 1 || s_iy[h + 1] != iy) g_hhi[d * BEV + iy] = h + 1;
        }
    }
}

// ---- k1: per-voxel counts ---------------------------------------------------
__global__ void count_kernel() {
    const int v = blockIdx.x * blockDim.x + threadIdx.x;
    if (v >= NVOX) return;
    const int iy = v / BEV, ix = v - iy * BEV;
    int cnt = 0;
    #pragma unroll
    for (int d = 0; d < D_N; ++d)
        cnt += (g_hhi[d * BEV + iy] - g_hlo[d * BEV + iy]) *
               (g_whi[d * BEV + ix] - g_wlo[d * BEV + ix]);
    g_cnt[v] = cnt;
}

// ---- k2: exclusive scan (single block, 1024 threads x 16 voxels) -------------
__global__ __launch_bounds__(1024) void scan_kernel() {
    __shared__ int sh[1024];
    const int t = threadIdx.x;
    int local[16], lsum = 0;
    #pragma unroll
    for (int j = 0; j < 16; ++j) {
        int v = t * 16 + j;
        int c = (v < NVOX) ? g_cnt[v] : 0;
        local[j] = lsum; lsum += c;
    }
    sh[t] = lsum;
    __syncthreads();
    for (int off = 1; off < 1024; off <<= 1) {
        int x = (t >= off) ? sh[t - off] : 0;
        __syncthreads();
        sh[t] += x;
        __syncthreads();
    }
    int base = sh[t] - lsum;     // exclusive
    #pragma unroll
    for (int j = 0; j < 16; ++j) {
        int v = t * 16 + j;
        if (v < NVOX) g_vstart[v] = base + local[j];
    }
    if (t == 1023) g_vstart[NVOX] = sh[1023];
}

// ---- k3: fill CSR entry list --------------------------------------------------
__global__ void fill_kernel() {
    const int v = blockIdx.x * blockDim.x + threadIdx.x;
    if (v >= NVOX) return;
    const int iy = v / BEV, ix = v - iy * BEV;
    int pos = g_vstart[v];
    for (int d = 0; d < D_N; ++d) {
        const int hl = g_hlo[d * BEV + iy], hh = g_hhi[d * BEV + iy];
        const int wl = g_wlo[d * BEV + ix], wh = g_whi[d * BEV + ix];
        for (int h = hl; h < hh; ++h)
            for (int w = wl; w < wh; ++w)
                g_entries[pos++] = make_int2(d * NPIX + h * W_N + w, v);
    }
}

// ---- k4: softmax + lift -------------------------------------------------------
__global__ __launch_bounds__(256, 8) void lift_kernel(
    const float* __restrict__ img_feat,
    const float* __restrict__ depth_logits)
{
    __shared__ float s_p[CAM_N][D_N];
    __shared__ float s_mx[CAM_N], s_inv[CAM_N];
    __shared__ int   s_dmax;

    const int p   = blockIdx.x;
    const int h   = p / W_N;
    const int w   = p - h * W_N;
    const int tid = threadIdx.x;
    const int cam = tid / D_N;
    const int d   = tid - cam * D_N;

    if (tid < CAM_N * D_N)
        s_p[cam][d] = depth_logits[((cam * D_N + d) * H_N + h) * W_N + w];
    __syncthreads();

    if (tid < CAM_N) {
        float m = -CUDART_INF_F;
        #pragma unroll
        for (int i = 0; i < D_N; ++i) m = fmaxf(m, s_p[tid][i]);
        s_mx[tid] = m;
    }
    __syncthreads();
    if (tid < CAM_N * D_N)
        s_p[cam][d] = __expf(s_p[cam][d] - s_mx[cam]);
    __syncthreads();
    if (tid < CAM_N) {
        float s = 0.0f;
        #pragma unroll
        for (int i = 0; i < D_N; ++i) s += s_p[tid][i];
        s_inv[tid] = 1.0f / s;
    }
    if (tid == CAM_N) {                  // validity is a prefix in d
        int dm = D_N;
        for (int i = 0; i < D_N; ++i) {
            float dv = (float)(i + 2);
            if (ix_of(w, dv) >= BEV || iy_of(h, dv) >= BEV) { dm = i; break; }
        }
        s_dmax = dm;
    }
    __syncthreads();
    if (tid < CAM_N * D_N)
        s_p[cam][d] *= s_inv[cam];
    __syncthreads();

    const int c    = tid & (C_N - 1);
    const int half = tid >> 7;
    const int fb   = (c * H_N + h) * W_N + w;
    const int FS   = C_N * H_N * W_N;
    const float f0 = img_feat[fb + 0 * FS];
    const float f1 = img_feat[fb + 1 * FS];
    const float f2 = img_feat[fb + 2 * FS];
    const float f3 = img_feat[fb + 3 * FS];
    const float f4 = img_feat[fb + 4 * FS];
    const float f5 = img_feat[fb + 5 * FS];

    const int dmax = s_dmax;
    for (int dd = half; dd < dmax; dd += 2) {
        float val = s_p[0][dd] * f0 + s_p[1][dd] * f1 + s_p[2][dd] * f2
                  + s_p[3][dd] * f3 + s_p[4][dd] * f4 + s_p[5][dd] * f5;
        g_T[((size_t)dd * NPIX + p) * C_N + c] = val;
    }
}

// ---- k5: chunked segmented splat ---------------------------------------------
// warp gw: z = gw&1 (channel half), chunk = gw>>1. lanes = 64 channels (float2).
__global__ __launch_bounds__(256) void splat_kernel()
{
    const int gw   = (blockIdx.x * blockDim.x + threadIdx.x) >> 5;
    const int lane = threadIdx.x & 31;
    const int z    = gw & 1;
    const int chunk = gw >> 1;

    const int total = g_vstart[NVOX];
    const int s0 = chunk * CHUNK;
    if (s0 >= total) return;
    const int s1 = min(s0 + CHUNK, total);

    const int prev_vox = (s0 > 0)     ? __ldg(&g_entries[s0 - 1]).y : -1;
    const int next_vox = (s1 < total) ? __ldg(&g_entries[s1]).y     : -1;

    const float2* __restrict__ T2 = reinterpret_cast<const float2*>(g_T);
    const int coff = z * 32 + lane;

    int2 e = __ldg(&g_entries[s0]);
    int  cur = e.y;
    bool first_seg = true;
    float ax = 0.0f, ay = 0.0f;

    for (int i = s0; i < s1; ++i) {
        float2 t = T2[(size_t)e.x * 64 + coff];
        int2 en = (i + 1 < s1) ? __ldg(&g_entries[i + 1]) : make_int2(0, -1);
        ax += t.x; ay += t.y;
        if (en.y != cur) {
            const bool partial = (first_seg && cur == prev_vox) ||
                                 (i + 1 == s1 && cur == next_vox);
            float* dst = g_acc + (size_t)cur * C_N + 2 * coff;
            if (partial) {
                asm volatile("red.global.add.v2.f32 [%0], {%1,%2};"
                             :: "l"(dst), "f"(ax), "f"(ay) : "memory");
            } else {
                *reinterpret_cast<float2*>(dst) = make_float2(ax, ay);
            }
            ax = 0.0f; ay = 0.0f;
            first_seg = false;
            cur = en.y;
        }
        e = en;
    }
}

// ---- k6: transpose g_acc (voxel-major) -> out (channel-major) -----------------
__global__ __launch_bounds__(256) void transpose_kernel(float* __restrict__ out)
{
    __shared__ float s[32][65];
    const int v0  = blockIdx.x * 32;
    const int z   = blockIdx.y;          // channel half
    const int tid = threadIdx.x;

    // read: consecutive threads -> consecutive channels (coalesced 256B)
    const int rc = tid & 63;             // channel-in-half
    const int rv = tid >> 6;             // 0..3
    #pragma unroll
    for (int j = 0; j < 8; ++j) {
        int vl = rv + 4 * j;
        int v  = v0 + vl;
        s[vl][rc] = (v < NVOX) ? g_acc[(size_t)v * C_N + z * 64 + rc] : 0.0f;
    }
    __syncthreads();

    // write: consecutive lanes -> consecutive voxels (coalesced 128B)
    const int vl = tid & 31;
    const int cb = tid >> 5;
    const int v  = v0 + vl;
    if (v < NVOX) {
        #pragma unroll
        for (int c = 0; c < 8; ++c)
            out[(size_t)(z * 64 + cb + 8 * c) * NVOX + v] = s[vl][cb + 8 * c];
    }
}

extern "C" void kernel_launch(void* const* d_in, const int* in_sizes, int n_in,
                              void* d_out, int out_size)
{
    const float* img_feat     = (const float*)d_in[0];
    const float* depth_logits = (const float*)d_in[1];
    float* out = (float*)d_out;

    void* acc_ptr = nullptr;
    cudaGetSymbolAddress(&acc_ptr, g_acc);
    cudaMemsetAsync(acc_ptr, 0, (size_t)NVOX * C_N * sizeof(float), 0);

    build_tables_kernel<<<D_N, 128>>>();
    count_kernel<<<(NVOX + 255) / 256, 256>>>();
    scan_kernel<<<1, 1024>>>();
    fill_kernel<<<(NVOX + 255) / 256, 256>>>();
    lift_kernel<<<NPIX, 256>>>(img_feat, depth_logits);
    splat_kernel<<<(2 * NCHUNK * 32 + 255) / 256, 256>>>();   // 440 blocks
    transpose_kernel<<<dim3((NVOX + 31) / 32, 2), 256>>>(out);
}

// round 8
// speedup vs baseline: 1.3565x; 1.0699x over previous
#include <cuda_runtime.h>
#include <math_constants.h>

// LSS view transformer, GB300 sm_103a — balanced CSR gather, issue-rate tuned.
//
// Pipeline (all static geometry rebuilt per launch, deterministic):
// k0 tables   : packed per-d run tables  wp[d][ix]=wlo|whi<<8, hp[d][iy]=...
// k1 count    : per-voxel entry counts (tables staged in smem -> LDS not LDG)
// k2 scan     : exclusive prefix sum over voxels (single block)
// k3 fill     : CSR entry list, packed (pxOff<<14 | voxel), smem tables
// k4 lift     : softmax over depth (6 cams) + T[d,p,c]=sum_cam prob*feat
// k5 splat    : fixed 64-entry chunks per warp; entries broadcast via shfl,
//               8 LDG.128 in flight; plain float4 stores for interior voxels,
//               red.v4 only at chunk boundaries
// k6 transpose: g_acc (voxel-major) -> out (channel-major)

#define D_N   40
#define H_N   32
#define W_N   88
#define CAM_N 6
#define C_N   128
#define BEV   125
#define NPIX  (H_N * W_N)          // 2816
#define NVOX  (BEV * BEV)          // 15625
#define NENT  (D_N * NPIX)         // 112640 upper bound
#define CHUNK 64
#define NWARP ((NENT + CHUNK - 1) / CHUNK)    // 1760

__device__ float g_T[(size_t)D_N * NPIX * C_N];   // ~57.7MB
__device__ float g_acc[(size_t)NVOX * C_N];       // ~8MB (voxel, channel)
__device__ int   g_wp[D_N * BEV];                 // wlo | whi<<8
__device__ int   g_hp[D_N * BEV];                 // hlo | hhi<<8
__device__ int   g_cnt[NVOX];
__device__ int   g_vstart[NVOX + 1];
__device__ int   g_entries[NENT];                 // (d*NPIX+h*W+w)<<14 | v

// Exact fp32 op sequence of the reference (unfused; no FMA contraction).
__device__ __forceinline__ int ix_of(int w, float dv) {
    float xd = __fmul_rn((float)w, dv);
    float gx = __fadd_rn(__fmul_rn(__fdiv_rn(xd, 3567.0f), 100.0f), -50.0f);
    return (int)__fdiv_rn(__fadd_rn(gx, 50.0f), 0.8f);
}
__device__ __forceinline__ int iy_of(int h, float dv) {
    float yd = __fmul_rn((float)h, dv);
    float gy = __fadd_rn(__fmul_rn(__fdiv_rn(yd, 1271.0f), 100.0f), -50.0f);
    return (int)__fdiv_rn(__fadd_rn(gy, 50.0f), 0.8f);
}

// ---- k0: packed run tables ---------------------------------------------------
__global__ void tables_kernel() {
    const int d = blockIdx.x;
    const int t = threadIdx.x;
    const float dv = (float)(d + 2);
    if (t < BEV) { g_wp[d * BEV + t] = 0; g_hp[d * BEV + t] = 0; }
    __syncthreads();
    if (t < W_N) {
        int ix = ix_of(t, dv);
        if (ix < BEV && (t == 0 || ix_of(t - 1, dv) != ix)) {
            int e = t + 1;
            while (e < W_N && ix_of(e, dv) == ix) ++e;
            g_wp[d * BEV + ix] = t | (e << 8);
        }
    } else if (t >= 96 && t < 96 + H_N) {
        int h = t - 96;
        int iy = iy_of(h, dv);
        if (iy < BEV && (h == 0 || iy_of(h - 1, dv) != iy)) {
            int e = h + 1;
            while (e < H_N && iy_of(e, dv) == iy) ++e;
            g_hp[d * BEV + iy] = h | (e << 8);
        }
    }
}

// ---- k1: per-voxel counts (tables in smem) -------------------------------------
__global__ __launch_bounds__(1024) void count_kernel() {
    __shared__ int s_w[D_N * BEV], s_h[D_N * BEV];
    for (int i = threadIdx.x; i < D_N * BEV; i += 1024) {
        s_w[i] = g_wp[i]; s_h[i] = g_hp[i];
    }
    __syncthreads();
    const int v = blockIdx.x * 1024 + threadIdx.x;
    if (v >= NVOX) return;
    const int iy = v / BEV, ix = v - iy * BEV;
    int cnt = 0;
    #pragma unroll
    for (int d = 0; d < D_N; ++d) {
        int wp = s_w[d * BEV + ix], hp = s_h[d * BEV + iy];
        cnt += ((hp >> 8) - (hp & 255)) * ((wp >> 8) - (wp & 255));
    }
    g_cnt[v] = cnt;
}

// ---- k2: exclusive scan (single block) ------------------------------------------
__global__ __launch_bounds__(1024) void scan_kernel() {
    __shared__ int sh[1024];
    const int t = threadIdx.x;
    int local[16], lsum = 0;
    #pragma unroll
    for (int j = 0; j < 16; ++j) {
        int v = t * 16 + j;
        int c = (v < NVOX) ? g_cnt[v] : 0;
        local[j] = lsum; lsum += c;
    }
    sh[t] = lsum;
    __syncthreads();
    for (int off = 1; off < 1024; off <<= 1) {
        int x = (t >= off) ? sh[t - off] : 0;
        __syncthreads();
        sh[t] += x;
        __syncthreads();
    }
    int base = sh[t] - lsum;
    #pragma unroll
    for (int j = 0; j < 16; ++j) {
        int v = t * 16 + j;
        if (v < NVOX) g_vstart[v] = base + local[j];
    }
    if (t == 1023) g_vstart[NVOX] = sh[1023];
}

// ---- k3: fill packed CSR entries (tables in smem) --------------------------------
__global__ __launch_bounds__(1024) void fill_kernel() {
    __shared__ int s_w[D_N * BEV], s_h[D_N * BEV];
    for (int i = threadIdx.x; i < D_N * BEV; i += 1024) {
        s_w[i] = g_wp[i]; s_h[i] = g_hp[i];
    }
    __syncthreads();
    const int v = blockIdx.x * 1024 + threadIdx.x;
    if (v >= NVOX) return;
    const int iy = v / BEV, ix = v - iy * BEV;
    int pos = g_vstart[v];
    #pragma unroll 1
    for (int d = 0; d < D_N; ++d) {
        int wp = s_w[d * BEV + ix], hp = s_h[d * BEV + iy];
        int wl = wp & 255, wh = wp >> 8;
        int hl = hp & 255, hh = hp >> 8;
        for (int h = hl; h < hh; ++h) {
            int pb = d * NPIX + h * W_N;
            for (int w = wl; w < wh; ++w)
                g_entries[pos++] = ((pb + w) << 14) | v;
        }
    }
}

// ---- k4: softmax + lift ------------------------------------------------------------
__global__ __launch_bounds__(256, 8) void lift_kernel(
    const float* __restrict__ img_feat,
    const float* __restrict__ depth_logits)
{
    __shared__ float s_p[CAM_N][D_N];
    __shared__ float s_mx[CAM_N], s_inv[CAM_N];
    __shared__ int   s_dmax;

    const int p   = blockIdx.x;
    const int h   = p / W_N;
    const int w   = p - h * W_N;
    const int tid = threadIdx.x;
    const int cam = tid / D_N;
    const int d   = tid - cam * D_N;

    if (tid < CAM_N * D_N)
        s_p[cam][d] = depth_logits[((cam * D_N + d) * H_N + h) * W_N + w];
    __syncthreads();

    if (tid < CAM_N) {
        float m = -CUDART_INF_F;
        #pragma unroll
        for (int i = 0; i < D_N; ++i) m = fmaxf(m, s_p[tid][i]);
        s_mx[tid] = m;
    }
    __syncthreads();
    if (tid < CAM_N * D_N)
        s_p[cam][d] = __expf(s_p[cam][d] - s_mx[cam]);
    __syncthreads();
    if (tid < CAM_N) {
        float s = 0.0f;
        #pragma unroll
        for (int i = 0; i < D_N; ++i) s += s_p[tid][i];
        s_inv[tid] = 1.0f / s;
    }
    if (tid == CAM_N) {                  // validity is a prefix in d
        int dm = D_N;
        for (int i = 0; i < D_N; ++i) {
            float dv = (float)(i + 2);
            if (ix_of(w, dv) >= BEV || iy_of(h, dv) >= BEV) { dm = i; break; }
        }
        s_dmax = dm;
    }
    __syncthreads();
    if (tid < CAM_N * D_N)
        s_p[cam][d] *= s_inv[cam];
    __syncthreads();

    const int c    = tid & (C_N - 1);
    const int half = tid >> 7;
    const int fb   = (c * H_N + h) * W_N + w;
    const int FS   = C_N * H_N * W_N;
    const float f0 = img_feat[fb + 0 * FS];
    const float f1 = img_feat[fb + 1 * FS];
    const float f2 = img_feat[fb + 2 * FS];
    const float f3 = img_feat[fb + 3 * FS];
    const float f4 = img_feat[fb + 4 * FS];
    const float f5 = img_feat[fb + 5 * FS];

    const int dmax = s_dmax;
    for (int dd = half; dd < dmax; dd += 2) {
        float val = s_p[0][dd] * f0 + s_p[1][dd] * f1 + s_p[2][dd] * f2
                  + s_p[3][dd] * f3 + s_p[4][dd] * f4 + s_p[5][dd] * f5;
        g_T[((size_t)dd * NPIX + p) * C_N + c] = val;
    }
}

// ---- k5: chunked segmented splat, MLP=8 ---------------------------------------------
__global__ __launch_bounds__(256) void splat_kernel()
{
    const int gw   = (blockIdx.x * 256 + threadIdx.x) >> 5;
    const int lane = threadIdx.x & 31;
    const int total = g_vstart[NVOX];
    const int s0 = gw * CHUNK;
    if (s0 >= total) return;
    const int cnt = min(CHUNK, total - s0);
    const unsigned FULL = 0xffffffffu;

    const int prev_vox = (s0 > 0)           ? (g_entries[s0 - 1]   & 0x3FFF) : -1;
    const int next_vox = (s0 + cnt < total) ? (g_entries[s0 + cnt] & 0x3FFF) : -1;

    // lane-held entries for the whole chunk (coalesced load, shfl broadcast)
    const int eA = g_entries[s0 + min(lane,      cnt - 1)];
    const int eB = g_entries[s0 + min(32 + lane, cnt - 1)];

    const float4* __restrict__ T4 = reinterpret_cast<const float4*>(g_T);

    float4 acc = make_float4(0.f, 0.f, 0.f, 0.f);
    int  cur   = __shfl_sync(FULL, eA, 0) & 0x3FFF;
    bool first = true;

    for (int base = 0; base < cnt; base += 8) {
        float4 tb[8];
        int    vn[8];
        #pragma unroll
        for (int j = 0; j < 8; ++j) {
            int i  = base + j;
            int e  = __shfl_sync(FULL, (i < 32) ? eA : eB, i & 31);
            if (i < cnt)
                tb[j] = T4[(size_t)(e >> 14) * 32 + lane];
            int i1 = i + 1;
            int e1 = __shfl_sync(FULL, (i1 < 32) ? eA : eB, i1 & 31);
            vn[j]  = (i1 < cnt) ? (e1 & 0x3FFF) : -1;
        }
        #pragma unroll
        for (int j = 0; j < 8; ++j) {
            int i = base + j;
            if (i >= cnt) break;
            acc.x += tb[j].x; acc.y += tb[j].y;
            acc.z += tb[j].z; acc.w += tb[j].w;
            if (vn[j] != cur) {
                float* dst = g_acc + (size_t)cur * C_N + lane * 4;
                bool partial = (first && cur == prev_vox) ||
                               (i + 1 == cnt && cur == next_vox);
                if (partial) {
                    asm volatile("red.global.add.v4.f32 [%0], {%1,%2,%3,%4};"
                                 :: "l"(dst), "f"(acc.x), "f"(acc.y),
                                    "f"(acc.z), "f"(acc.w) : "memory");
                } else {
                    *reinterpret_cast<float4*>(dst) = acc;
                }
                acc   = make_float4(0.f, 0.f, 0.f, 0.f);
                first = false;
                cur   = vn[j];
            }
        }
    }
}

// ---- k6: transpose g_acc (voxel-major) -> out (channel-major) ------------------------
__global__ __launch_bounds__(256) void transpose_kernel(float* __restrict__ out)
{
    __shared__ float s[32][65];
    const int v0  = blockIdx.x * 32;
    const int z   = blockIdx.y;          // channel half
    const int tid = threadIdx.x;

    const int rc = tid & 63;
    const int rv = tid >> 6;
    #pragma unroll
    for (int j = 0; j < 8; ++j) {
        int vl = rv + 4 * j;
        int v  = v0 + vl;
        s[vl][rc] = (v < NVOX) ? g_acc[(size_t)v * C_N + z * 64 + rc] : 0.0f;
    }
    __syncthreads();

    const int vl = tid & 31;
    const int cb = tid >> 5;
    const int v  = v0 + vl;
    if (v < NVOX) {
        #pragma unroll
        for (int c = 0; c < 8; ++c)
            out[(size_t)(z * 64 + cb + 8 * c) * NVOX + v] = s[vl][cb + 8 * c];
    }
}

extern "C" void kernel_launch(void* const* d_in, const int* in_sizes, int n_in,
                              void* d_out, int out_size)
{
    const float* img_feat     = (const float*)d_in[0];
    const float* depth_logits = (const float*)d_in[1];
    float* out = (float*)d_out;

    void* acc_ptr = nullptr;
    cudaGetSymbolAddress(&acc_ptr, g_acc);
    cudaMemsetAsync(acc_ptr, 0, (size_t)NVOX * C_N * sizeof(float), 0);

    tables_kernel<<<D_N, 128>>>();
    count_kernel<<<(NVOX + 1023) / 1024, 1024>>>();
    scan_kernel<<<1, 1024>>>();
    fill_kernel<<<(NVOX + 1023) / 1024, 1024>>>();
    lift_kernel<<<NPIX, 256>>>(img_feat, depth_logits);
    splat_kernel<<<(NWARP * 32 + 255) / 256, 256>>>();
    transpose_kernel<<<dim3((NVOX + 31) / 32, 2), 256>>>(out);
}

// round 9
// speedup vs baseline: 1.9609x; 1.4456x over previous
#include <cuda_runtime.h>
#include <math_constants.h>

// LSS view transformer, GB300 sm_103a — balanced CSR gather v3.
//
// k1 count : per-voxel entry counts + per-(voxel,d) exclusive offsets (dpre);
//            run tables rebuilt in smem per block (no table kernel).
// k2 scan  : exclusive prefix sum over voxels (single block, shfl scan).
// k3 fill  : ONE THREAD PER (d,pixel); position = vstart[v] + dpre[d][v] +
//            closed-form rank inside the (d, rect) — perfectly balanced.
// k4 lift  : (2h x 8w) pixel tiles; feats read as float4 (sector-exact 11MB),
//            probs smem-staged; T[d,p,c] stores 128B-coalesced (~57.7MB).
// k5 splat : fixed 64-entry chunks per warp, entries shfl-broadcast, 8
//            LDG.128 in flight, plain float4 stores interior / red.v4 at
//            chunk boundaries only.
// k6 transpose: g_acc (voxel-major) -> out (channel-major).

#define D_N   40
#define H_N   32
#define W_N   88
#define CAM_N 6
#define C_N   128
#define BEV   125
#define NPIX  (H_N * W_N)          // 2816
#define NVOX  (BEV * BEV)          // 15625
#define NENT  (D_N * NPIX)         // 112640 upper bound
#define CHUNK 64
#define NWARP ((NENT + CHUNK - 1) / CHUNK)

__device__ float g_T[(size_t)D_N * NPIX * C_N];   // ~57.7MB
__device__ float g_acc[(size_t)NVOX * C_N];       // ~8MB (voxel, channel)
__device__ int   g_cnt[NVOX];
__device__ int   g_vstart[NVOX + 1];
__device__ int   g_dpre[D_N * NVOX];              // [d][v] exclusive offsets
__device__ int   g_entries[NENT];                 // (d*NPIX+p)<<14 | v

// Exact fp32 op sequence of the reference (unfused; no FMA contraction).
__device__ __forceinline__ int ix_of(int w, float dv) {
    float xd = __fmul_rn((float)w, dv);
    float gx = __fadd_rn(__fmul_rn(__fdiv_rn(xd, 3567.0f), 100.0f), -50.0f);
    return (int)__fdiv_rn(__fadd_rn(gx, 50.0f), 0.8f);
}
__device__ __forceinline__ int iy_of(int h, float dv) {
    float yd = __fmul_rn((float)h, dv);
    float gy = __fadd_rn(__fmul_rn(__fdiv_rn(yd, 1271.0f), 100.0f), -50.0f);
    return (int)__fdiv_rn(__fadd_rn(gy, 50.0f), 0.8f);
}

// Build packed run tables in smem: wp[d*BEV+ix] = wlo|whi<<8, hp likewise.
__device__ __forceinline__ void build_runs(int* s_wp, int* s_hp, int tid) {
    for (int i = tid; i < D_N * BEV; i += 1024) { s_wp[i] = 0; s_hp[i] = 0; }
    __syncthreads();
    for (int i = tid; i < D_N * W_N; i += 1024) {
        int d = i / W_N, w = i - d * W_N;
        float dv = (float)(d + 2);
        int ix = ix_of(w, dv);
        if (ix < BEV && (w == 0 || ix_of(w - 1, dv) != ix)) {
            int e = w + 1;
            while (e < W_N && ix_of(e, dv) == ix) ++e;
            s_wp[d * BEV + ix] = w | (e << 8);
        }
    }
    for (int i = tid; i < D_N * H_N; i += 1024) {
        int d = i / H_N, h = i - d * H_N;
        float dv = (float)(d + 2);
        int iy = iy_of(h, dv);
        if (iy < BEV && (h == 0 || iy_of(h - 1, dv) != iy)) {
            int e = h + 1;
            while (e < H_N && iy_of(e, dv) == iy) ++e;
            s_hp[d * BEV + iy] = h | (e << 8);
        }
    }
    __syncthreads();
}

// ---- k1: counts + per-d offsets ----------------------------------------------
__global__ __launch_bounds__(1024) void count_kernel() {
    __shared__ int s_wp[D_N * BEV], s_hp[D_N * BEV];   // 40KB
    build_runs(s_wp, s_hp, threadIdx.x);
    const int v = blockIdx.x * 1024 + threadIdx.x;
    if (v >= NVOX) return;
    const int iy = v / BEV, ix = v - iy * BEV;
    int run = 0;
    #pragma unroll
    for (int d = 0; d < D_N; ++d) {
        int wp = s_wp[d * BEV + ix], hp = s_hp[d * BEV + iy];
        g_dpre[d * NVOX + v] = run;
        run += ((hp >> 8) - (hp & 255)) * ((wp >> 8) - (wp & 255));
    }
    g_cnt[v] = run;
}

// ---- k2: exclusive scan (shfl) -------------------------------------------------
__global__ __launch_bounds__(1024) void scan_kernel() {
    __shared__ int s_ws[32];
    const int t = threadIdx.x, lane = t & 31, wid = t >> 5;
    int local[16], lsum = 0;
    #pragma unroll
    for (int j = 0; j < 16; ++j) {
        int v = t * 16 + j;
        int c = (v < NVOX) ? g_cnt[v] : 0;
        local[j] = lsum; lsum += c;
    }
    int x = lsum;
    #pragma unroll
    for (int off = 1; off < 32; off <<= 1) {
        int y = __shfl_up_sync(0xffffffffu, x, off);
        if (lane >= off) x += y;
    }
    if (lane == 31) s_ws[wid] = x;
    __syncthreads();
    if (wid == 0) {
        int y = s_ws[lane];
        #pragma unroll
        for (int off = 1; off < 32; off <<= 1) {
            int z = __shfl_up_sync(0xffffffffu, y, off);
            if (lane >= off) y += z;
        }
        s_ws[lane] = y;
    }
    __syncthreads();
    const int base = x - lsum + ((wid > 0) ? s_ws[wid - 1] : 0);
    #pragma unroll
    for (int j = 0; j < 16; ++j) {
        int v = t * 16 + j;
        if (v < NVOX) g_vstart[v] = base + local[j];
    }
    if (t == 1023) g_vstart[NVOX] = base + lsum;
}

// ---- k3: fill, one thread per (d,pixel) ----------------------------------------
__global__ __launch_bounds__(1024) void fill_kernel() {
    __shared__ int s_wp[D_N * BEV], s_hp[D_N * BEV];
    build_runs(s_wp, s_hp, threadIdx.x);
    const int idx = blockIdx.x * 1024 + threadIdx.x;
    if (idx >= NENT) return;
    const int d = idx / NPIX, p = idx - d * NPIX;
    const int h = p / W_N,   w = p - h * W_N;
    const float dv = (float)(d + 2);
    const int ix = ix_of(w, dv), iy = iy_of(h, dv);
    if (ix >= BEV || iy >= BEV) return;
    const int v  = iy * BEV + ix;
    const int wp = s_wp[d * BEV + ix], hp = s_hp[d * BEV + iy];
    const int wl = wp & 255, wh = wp >> 8, hl = hp & 255;
    const int rank = (h - hl) * (wh - wl) + (w - wl);
    const int pos  = g_vstart[v] + g_dpre[d * NVOX + v] + rank;
    g_entries[pos] = (idx << 14) | v;
}

// ---- k4: lift (2h x 8w tile) -----------------------------------------------------
__global__ __launch_bounds__(256) void lift_kernel(
    const float* __restrict__ img_feat,
    const float* __restrict__ depth_logits)
{
    __shared__ __align__(16) float s_l[CAM_N][D_N][16];  // [cam][d][hsub*8+pl]
    __shared__ float s_mx[CAM_N][16], s_inv[CAM_N][16];

    const int h0  = (blockIdx.x / 11) * 2;
    const int w0  = (blockIdx.x % 11) * 8;
    const int tid = threadIdx.x;

    // stage logits: 6*40*16 floats, 32B-chunk coalesced
    for (int i = tid; i < CAM_N * D_N * 16; i += 256) {
        int cam = i / (D_N * 16), r = i - cam * D_N * 16;
        int d = r >> 4, pp = r & 15, hs = pp >> 3, pl = pp & 7;
        s_l[cam][d][pp] =
            depth_logits[((cam * D_N + d) * H_N + h0 + hs) * W_N + w0 + pl];
    }
    __syncthreads();
    if (tid < CAM_N * 16) {
        int cam = tid >> 4, pp = tid & 15;
        float m = -CUDART_INF_F;
        #pragma unroll
        for (int d = 0; d < D_N; ++d) m = fmaxf(m, s_l[cam][d][pp]);
        s_mx[cam][pp] = m;
    }
    __syncthreads();
    for (int i = tid; i < CAM_N * D_N * 16; i += 256) {
        int cam = i / (D_N * 16), r = i - cam * D_N * 16;
        int d = r >> 4, pp = r & 15;
        s_l[cam][d][pp] = __expf(s_l[cam][d][pp] - s_mx[cam][pp]);
    }
    __syncthreads();
    if (tid < CAM_N * 16) {
        int cam = tid >> 4, pp = tid & 15;
        float s = 0.0f;
        #pragma unroll
        for (int d = 0; d < D_N; ++d) s += s_l[cam][d][pp];
        s_inv[cam][pp] = 1.0f / s;
    }
    __syncthreads();
    for (int i = tid; i < CAM_N * D_N * 16; i += 256) {
        int cam = i / (D_N * 16), r = i - cam * D_N * 16;
        int d = r >> 4, pp = r & 15;
        s_l[cam][d][pp] *= s_inv[cam][pp];
    }
    __syncthreads();

    // feats: 8 w-consecutive floats per cam, sector-exact float4 pairs
    const int c  = tid & (C_N - 1);
    const int hs = tid >> 7;              // warp 0-3: h0, warp 4-7: h0+1
    const int FS = C_N * H_N * W_N;
    float4 fr[CAM_N][2];
    #pragma unroll
    for (int cam = 0; cam < CAM_N; ++cam) {
        const float4* fp = reinterpret_cast<const float4*>(
            img_feat + cam * FS + (c * H_N + h0 + hs) * W_N + w0);
        fr[cam][0] = fp[0];
        fr[cam][1] = fp[1];
    }

    const int pixbase = (h0 + hs) * W_N + w0;
    #pragma unroll 1
    for (int d = 0; d < D_N; ++d) {
        float* dst = g_T + ((size_t)d * NPIX + pixbase) * C_N + c;
        float4 q0[CAM_N], q1[CAM_N];
        #pragma unroll
        for (int cam = 0; cam < CAM_N; ++cam) {
            q0[cam] = *reinterpret_cast<const float4*>(&s_l[cam][d][hs * 8]);
            q1[cam] = *reinterpret_cast<const float4*>(&s_l[cam][d][hs * 8 + 4]);
        }
        float val[8];
        #pragma unroll
        for (int j = 0; j < 8; ++j) val[j] = 0.0f;
        #pragma unroll
        for (int cam = 0; cam < CAM_N; ++cam) {
            val[0] += q0[cam].x * fr[cam][0].x;
            val[1] += q0[cam].y * fr[cam][0].y;
            val[2] += q0[cam].z * fr[cam][0].z;
            val[3] += q0[cam].w * fr[cam][0].w;
            val[4] += q1[cam].x * fr[cam][1].x;
            val[5] += q1[cam].y * fr[cam][1].y;
            val[6] += q1[cam].z * fr[cam][1].z;
            val[7] += q1[cam].w * fr[cam][1].w;
        }
        #pragma unroll
        for (int j = 0; j < 8; ++j)
            dst[(size_t)j * C_N] = val[j];
    }
}

// ---- k5: chunked segmented splat, MLP=8 ------------------------------------------
__global__ __launch_bounds__(256) void splat_kernel()
{
    const int gw   = (blockIdx.x * 256 + threadIdx.x) >> 5;
    const int lane = threadIdx.x & 31;
    const int total = g_vstart[NVOX];
    const int s0 = gw * CHUNK;
    if (s0 >= total) return;
    const int cnt = min(CHUNK, total - s0);
    const unsigned FULL = 0xffffffffu;

    const int prev_vox = (s0 > 0)           ? (g_entries[s0 - 1]   & 0x3FFF) : -1;
    const int next_vox = (s0 + cnt < total) ? (g_entries[s0 + cnt] & 0x3FFF) : -1;

    const int eA = g_entries[s0 + min(lane,      cnt - 1)];
    const int eB = g_entries[s0 + min(32 + lane, cnt - 1)];

    const float4* __restrict__ T4 = reinterpret_cast<const float4*>(g_T);

    float4 acc = make_float4(0.f, 0.f, 0.f, 0.f);
    int  cur   = __shfl_sync(FULL, eA, 0) & 0x3FFF;
    bool first = true;

    for (int base = 0; base < cnt; base += 8) {
        float4 tb[8];
        int    vn[8];
        #pragma unroll
        for (int j = 0; j < 8; ++j) {
            int i = base + j;
            int e = __shfl_sync(FULL, (i < 32) ? eA : eB, i & 31);
            if (i < cnt)
                tb[j] = T4[(size_t)(e >> 14) * 32 + lane];
            int i1 = i + 1;
            int e1 = __shfl_sync(FULL, (i1 < 32) ? eA : eB, i1 & 31);
            vn[j]  = (i1 < cnt) ? (e1 & 0x3FFF) : -1;
        }
        #pragma unroll
        for (int j = 0; j < 8; ++j) {
            int i = base + j;
            if (i >= cnt) break;
            acc.x += tb[j].x; acc.y += tb[j].y;
            acc.z += tb[j].z; acc.w += tb[j].w;
            if (vn[j] != cur) {
                float* dst = g_acc + (size_t)cur * C_N + lane * 4;
                bool partial = (first && cur == prev_vox) ||
                               (i + 1 == cnt && cur == next_vox);
                if (partial) {
                    asm volatile("red.global.add.v4.f32 [%0], {%1,%2,%3,%4};"
                                 :: "l"(dst), "f"(acc.x), "f"(acc.y),
                                    "f"(acc.z), "f"(acc.w) : "memory");
                } else {
                    *reinterpret_cast<float4*>(dst) = acc;
                }
                acc   = make_float4(0.f, 0.f, 0.f, 0.f);
                first = false;
                cur   = vn[j];
            }
        }
    }
}

// ---- k6: transpose g_acc (voxel-major) -> out (channel-major) ---------------------
__global__ __launch_bounds__(256) void transpose_kernel(float* __restrict__ out)
{
    __shared__ float s[32][65];
    const int v0  = blockIdx.x * 32;
    const int z   = blockIdx.y;
    const int tid = threadIdx.x;

    const int rc = tid & 63;
    const int rv = tid >> 6;
    #pragma unroll
    for (int j = 0; j < 8; ++j) {
        int vl = rv + 4 * j;
        int v  = v0 + vl;
        s[vl][rc] = (v < NVOX) ? g_acc[(size_t)v * C_N + z * 64 + rc] : 0.0f;
    }
    __syncthreads();

    const int vl = tid & 31;
    const int cb = tid >> 5;
    const int v  = v0 + vl;
    if (v < NVOX) {
        #pragma unroll
        for (int c = 0; c < 8; ++c)
            out[(size_t)(z * 64 + cb + 8 * c) * NVOX + v] = s[vl][cb + 8 * c];
    }
}

extern "C" void kernel_launch(void* const* d_in, const int* in_sizes, int n_in,
                              void* d_out, int out_size)
{
    const float* img_feat     = (const float*)d_in[0];
    const float* depth_logits = (const float*)d_in[1];
    float* out = (float*)d_out;

    void* acc_ptr = nullptr;
    cudaGetSymbolAddress(&acc_ptr, g_acc);
    cudaMemsetAsync(acc_ptr, 0, (size_t)NVOX * C_N * sizeof(float), 0);

    count_kernel<<<(NVOX + 1023) / 1024, 1024>>>();
    scan_kernel<<<1, 1024>>>();
    fill_kernel<<<(NENT + 1023) / 1024, 1024>>>();
    lift_kernel<<<(H_N / 2) * (W_N / 8), 256>>>(img_feat, depth_logits);
    splat_kernel<<<(NWARP * 32 + 255) / 256, 256>>>();
    transpose_kernel<<<dim3((NVOX + 31) / 32, 2), 256>>>(out);
}